// round 14
// baseline (speedup 1.0000x reference)
#include <cuda_runtime.h>
#include <cuda_bf16.h>
#include <math.h>
#include <stdint.h>

#define NNODES 50000
#define TT 8
#define HH 128
#define COUT 32
#define EDGES 800000
#define MROWS 400000

typedef unsigned short ushort_t;

// ======================= scratch (device globals) ============================
// All GEMM operands stored as uint2 {hi_bf16x2, lo_bf16x2} per k-pair.
__device__ int   g_is64;
__device__ int   g_src[EDGES];
__device__ int   g_dst[EDGES];
__device__ int   g_cnt[NNODES];
__device__ int   g_off[NNODES];
__device__ int   g_cur[NNODES];
__device__ int   g_adj[EDGES];
__device__ float g_GX [(size_t)MROWS*3*HH];    // [m, 384] fp32
__device__ float g_bh [96];
__device__ uint2 g_AX2 [(size_t)MROWS*32];     // [m, 32 pairs]  (64 k)
__device__ uint2 g_Wcat2[128*32];              // [128, 32 pairs]
__device__ uint2 g_Wih2 [384*64];              // [384, 64 pairs]
__device__ uint2 g_Whh2 [384*64];
__device__ uint2 g_Whd2 [96*64];
__device__ uint2 g_H2  [(size_t)NNODES*64];    // [n, 64 pairs]
__device__ uint2 g_HS2 [(size_t)MROWS*64];     // [m, 64 pairs]

// ======================= helpers =============================================
__device__ __forceinline__ void bsplit1(float v, ushort_t& h, ushort_t& l) {
    __nv_bfloat16 hb = __float2bfloat16_rn(v);
    __nv_bfloat16 lb = __float2bfloat16_rn(v - __bfloat162float(hb));
    h = __bfloat16_as_ushort(hb); l = __bfloat16_as_ushort(lb);
}
__device__ __forceinline__ uint2 bpack2(float v0, float v1) {
    ushort_t h0, l0, h1, l1;
    bsplit1(v0, h0, l0); bsplit1(v1, h1, l1);
    uint2 r;
    r.x = ((uint32_t)h1 << 16) | h0;
    r.y = ((uint32_t)l1 << 16) | l0;
    return r;
}
__device__ __forceinline__ float2 bunpack2(uint2 v) {
    float2 r;
    r.x = __bfloat162float(__ushort_as_bfloat16((ushort_t)(v.x & 0xffff)))
        + __bfloat162float(__ushort_as_bfloat16((ushort_t)(v.y & 0xffff)));
    r.y = __bfloat162float(__ushort_as_bfloat16((ushort_t)(v.x >> 16)))
        + __bfloat162float(__ushort_as_bfloat16((ushort_t)(v.y >> 16)));
    return r;
}
#define MMA_BF16(C, Af, Bf) \
    asm volatile( \
        "mma.sync.aligned.m16n8k16.row.col.f32.bf16.bf16.f32 " \
        "{%0,%1,%2,%3}, {%4,%5,%6,%7}, {%8,%9}, {%0,%1,%2,%3};" \
        : "+f"((C)[0]), "+f"((C)[1]), "+f"((C)[2]), "+f"((C)[3]) \
        : "r"((Af)[0]), "r"((Af)[1]), "r"((Af)[2]), "r"((Af)[3]), \
          "r"((Bf)[0]), "r"((Bf)[1]))
#define CP_ASYNC16(dst, src, sz) \
    asm volatile("cp.async.ca.shared.global [%0], [%1], 16, %2;" \
                 :: "r"(dst), "l"(src), "r"(sz))
#define CP_COMMIT() asm volatile("cp.async.commit_group;" ::: "memory")
#define CP_WAIT1()  asm volatile("cp.async.wait_group 1;" ::: "memory")
#define CP_WAIT0()  asm volatile("cp.async.wait_group 0;" ::: "memory")
__device__ __forceinline__ float sigmoidf_(float v) { return 1.f / (1.f + expf(-v)); }

// load A frag (hi+lo) from interleaved uint2 tile, stride S pairs
#define LD_A(afh, afl, T, S, r, kb) do { \
    uint2 _v0 = (T)[ (r)   *(S) + (kb)    ]; \
    uint2 _v1 = (T)[((r)+8)*(S) + (kb)    ]; \
    uint2 _v2 = (T)[ (r)   *(S) + (kb) + 4]; \
    uint2 _v3 = (T)[((r)+8)*(S) + (kb) + 4]; \
    (afh)[0]=_v0.x; (afl)[0]=_v0.y; (afh)[1]=_v1.x; (afl)[1]=_v1.y; \
    (afh)[2]=_v2.x; (afl)[2]=_v2.y; (afh)[3]=_v3.x; (afl)[3]=_v3.y; \
} while (0)
#define LD_B(bfh, bfl, T, S, cb, kb) do { \
    uint2 _u0 = (T)[(cb)*(S) + (kb)    ]; \
    uint2 _u1 = (T)[(cb)*(S) + (kb) + 4]; \
    (bfh)[0]=_u0.x; (bfl)[0]=_u0.y; (bfh)[1]=_u1.x; (bfl)[1]=_u1.y; \
} while (0)

// ======================= edge dtype detect + convert =========================
__global__ void detect_kernel(const void* ei) {
    const unsigned long long* p = (const unsigned long long*)ei;
    int is64 = 1;
    for (int i = 0; i < 1024; i++)
        if ((p[i] >> 32) != 0ull) { is64 = 0; break; }
    g_is64 = is64;
}
__global__ void convert_kernel(const void* ei) {
    int e = blockIdx.x * blockDim.x + threadIdx.x;
    if (e >= EDGES) return;
    int s, d;
    if (g_is64) {
        const long long* p = (const long long*)ei;
        s = (int)p[e]; d = (int)p[EDGES + e];
    } else {
        const int* p = (const int*)ei;
        s = p[e]; d = p[EDGES + e];
    }
    s = min(max(s, 0), NNODES - 1);
    d = min(max(d, 0), NNODES - 1);
    g_src[e] = s;
    g_dst[e] = d;
}

// ======================= graph prep ==========================================
__global__ void zero_kernel() {
    int idx = blockIdx.x * blockDim.x + threadIdx.x;
    int stride = gridDim.x * blockDim.x;
    for (int i = idx; i < NNODES; i += stride) g_cnt[i] = 0;
}
__global__ void count_kernel() {
    int e = blockIdx.x * blockDim.x + threadIdx.x;
    if (e < EDGES) atomicAdd(&g_cnt[g_dst[e]], 1);
}
__global__ void scan_kernel() {
    __shared__ int partial[1024];
    const int CH = (NNODES + 1023) / 1024;
    int t = threadIdx.x;
    int begin = t * CH;
    int end   = min(begin + CH, NNODES);
    int s = 0;
    for (int i = begin; i < end; i++) s += g_cnt[i];
    partial[t] = s;
    __syncthreads();
    #pragma unroll
    for (int d = 1; d < 1024; d <<= 1) {
        int v = (t >= d) ? partial[t - d] : 0;
        __syncthreads();
        partial[t] += v;
        __syncthreads();
    }
    int off = partial[t] - s;
    for (int i = begin; i < end; i++) {
        g_off[i] = off;
        g_cur[i] = off;
        off += g_cnt[i];
    }
}
__global__ void fill_kernel() {
    int e = blockIdx.x * blockDim.x + threadIdx.x;
    if (e >= EDGES) return;
    int pos = atomicAdd(&g_cur[g_dst[e]], 1);
    g_adj[pos] = g_src[e];
}
__global__ void __launch_bounds__(256) gather_kernel(const float* __restrict__ x) {
    int n   = blockIdx.x;
    int idx = threadIdx.x;
    int lane = idx & 31;
    int beg = g_off[n];
    int cnt = g_cnt[n];
    float s = 0.f;
    for (int p = beg; p < beg + cnt; p++) {
        int src = g_adj[p];
        s += x[(size_t)src * 256 + idx];
    }
    float dg = fmaxf((float)cnt, 1.f);
    int t = idx >> 5, c = idx & 31;
    size_t m = (size_t)n * 8 + t;
    float va = s / dg;
    float vx = x[(size_t)n * 256 + idx];
    ushort_t ha, la, hx, lx;
    bsplit1(va, ha, la);
    bsplit1(vx, hx, lx);
    uint32_t oha = __shfl_down_sync(0xffffffffu, (uint32_t)ha, 1);
    uint32_t ola = __shfl_down_sync(0xffffffffu, (uint32_t)la, 1);
    uint32_t ohx = __shfl_down_sync(0xffffffffu, (uint32_t)hx, 1);
    uint32_t olx = __shfl_down_sync(0xffffffffu, (uint32_t)lx, 1);
    if (!(lane & 1)) {
        uint2 pa, px;
        pa.x = (oha << 16) | ha; pa.y = (ola << 16) | la;
        px.x = (ohx << 16) | hx; px.y = (olx << 16) | lx;
        g_AX2[m*32 + (c >> 1)]      = pa;
        g_AX2[m*32 + 16 + (c >> 1)] = px;
    }
}
// weight conversions: one thread per k-pair
__global__ void wcat2_kernel(const float* __restrict__ Wl, const float* __restrict__ Wr) {
    int idx = blockIdx.x * blockDim.x + threadIdx.x;
    if (idx >= 128*32) return;
    int j = idx >> 5, p = idx & 31;
    int c = p*2;
    float v0 = (c < 32)     ? Wl[j*32 + c]     : Wr[j*32 + (c-32)];
    float v1 = (c+1 < 32)   ? Wl[j*32 + c+1]   : Wr[j*32 + (c+1-32)];
    g_Wcat2[idx] = bpack2(v0, v1);
}
__global__ void wih2_kernel(const float* __restrict__ W_ih) {
    int idx = blockIdx.x * blockDim.x + threadIdx.x;
    if (idx >= 384*64) return;
    g_Wih2[idx] = bpack2(W_ih[idx*2], W_ih[idx*2+1]);
}
__global__ void whh2_kernel(const float* __restrict__ W_hh) {
    int idx = blockIdx.x * blockDim.x + threadIdx.x;
    if (idx >= 384*64) return;
    g_Whh2[idx] = bpack2(W_hh[idx*2], W_hh[idx*2+1]);
}
__global__ void whd2_kernel(const float* __restrict__ W_rec, const float* __restrict__ b_rec,
                            const float* __restrict__ W_c1,  const float* __restrict__ b_c1) {
    int idx = blockIdx.x * blockDim.x + threadIdx.x;
    if (idx < 96*64) {
        int r = idx >> 6, p = idx & 63;
        const float* src = (r < 32) ? (W_rec + r*128) : (W_c1 + (r-32)*128);
        g_Whd2[idx] = bpack2(src[p*2], src[p*2+1]);
    }
    if (idx < 96) g_bh[idx] = (idx < 32) ? b_rec[idx] : b_c1[idx - 32];
}

// ======================= t=0 GRU (H0 = 0 => gh = b_hh) =======================
__global__ void gru0_kernel(const float* __restrict__ b_hh) {
    int idx = blockIdx.x * blockDim.x + threadIdx.x;
    if (idx >= NNODES*HH) return;
    int i = idx >> 7, j = idx & 127;
    int lane = threadIdx.x & 31;
    size_t m = (size_t)i*8;
    float r  = sigmoidf_(g_GX[m*384 + j]       + b_hh[j]);
    float z  = sigmoidf_(g_GX[m*384 + 128 + j] + b_hh[128 + j]);
    float nn = tanhf(g_GX[m*384 + 256 + j] + r * b_hh[256 + j]);
    float hn = (1.f - z)*nn;
    ushort_t h, l;
    bsplit1(hn, h, l);
    uint32_t oh = __shfl_down_sync(0xffffffffu, (uint32_t)h, 1);
    uint32_t ol = __shfl_down_sync(0xffffffffu, (uint32_t)l, 1);
    if (!(lane & 1)) {
        uint2 v;
        v.x = (oh << 16) | h; v.y = (ol << 16) | l;
        g_H2 [(size_t)i*64 + (j >> 1)] = v;
        g_HS2[m*64 + (j >> 1)]         = v;
    }
}

// ======================= tiling constants (uint2 units) ======================
#define PR 20                          /* pairs per 32k-chunk row (16 + 4 pad) */
#define A128P (128*PR)                 /* 2560 uint2 */
#define STGP (2*A128P)                 /* A+B per stage = 5120 uint2 = 40 KB */
#define C1S  72

// ======================= fused SP+GX kernel ==================================
#define SPP 68                         /* SP tile stride (64 pairs + 4 pad) */
#define SPOFF (2*STGP)                 /* 10240 uint2 */
#define SPX_SMEM ((SPOFF + 128*SPP)*8) /* 151552 B */

__global__ void __launch_bounds__(512, 1) spgx_kernel(
    const float* __restrict__ bl, const float* __restrict__ b_ih)
{
    extern __shared__ uint2 sm2[];
    uint32_t smem_b;
    asm("{ .reg .u64 t; cvta.to.shared.u64 t, %1; cvt.u32.u64 %0, t; }"
        : "=r"(smem_b) : "l"(sm2));

    const int tid  = threadIdx.x;
    const int lane = tid & 31;
    const int w    = tid >> 5;
    const int gid  = lane >> 2;
    const int tig  = lane & 3;
    const int wm   = w >> 2;
    const int wn   = w & 3;
    const int bm   = blockIdx.x * 128;
    uint2* SP2 = sm2 + SPOFF;

    float acc[2][4][4];
    #pragma unroll
    for (int i = 0; i < 2; i++)
        #pragma unroll
        for (int j = 0; j < 4; j++)
            #pragma unroll
            for (int k = 0; k < 4; k++) acc[i][j][k] = 0.f;

    // ---------------- phase 1: SP = relu(AX @ Wcat^T + bl) ----------------
    // copies: A 128 rows x 8 segs(16B=2 pairs) = 1024 -> 2/thr; B same
    auto issue_copy1 = [&](int kc) {
        const uint32_t sb = smem_b + (uint32_t)((kc & 1) * STGP) * 8u;
        #pragma unroll
        for (int h = 0; h < 2; h++) {
            int i = tid + h*512;
            int row = i >> 3, seg = i & 7;
            uint32_t soff = (uint32_t)(row * PR + seg * 2) * 8u;
            CP_ASYNC16(sb + soff, g_AX2 + (size_t)(bm + row)*32 + kc*16 + seg*2, 16);
            CP_ASYNC16(sb + (uint32_t)A128P*8u + soff,
                       g_Wcat2 + (size_t)row*32 + kc*16 + seg*2, 16);
        }
        CP_COMMIT();
    };

    issue_copy1(0);
    for (int kc = 0; kc < 2; kc++) {
        if (kc == 0) { issue_copy1(1); CP_WAIT1(); } else { CP_WAIT0(); }
        __syncthreads();
        const uint2* A2 = sm2 + (kc & 1) * STGP;
        const uint2* B2 = A2 + A128P;
        #pragma unroll
        for (int ks = 0; ks < 2; ks++) {
            const int kb = ks*8 + tig;
            uint32_t afh[2][4], afl[2][4];
            #pragma unroll
            for (int mt = 0; mt < 2; mt++)
                LD_A(afh[mt], afl[mt], A2, PR, wm*32 + mt*16 + gid, kb);
            #pragma unroll
            for (int nt = 0; nt < 4; nt++) {
                int cb = wn*32 + nt*8 + gid;
                uint32_t bfh[2], bfl[2];
                LD_B(bfh, bfl, B2, PR, cb, kb);
                #pragma unroll
                for (int mt = 0; mt < 2; mt++) {
                    MMA_BF16(acc[mt][nt], afh[mt], bfh);
                    MMA_BF16(acc[mt][nt], afh[mt], bfl);
                    MMA_BF16(acc[mt][nt], afl[mt], bfh);
                }
            }
        }
        __syncthreads();
    }
    // stage relu(SP) split -> interleaved SP tile
    #pragma unroll
    for (int mt = 0; mt < 2; mt++)
        #pragma unroll
        for (int nt = 0; nt < 4; nt++) {
            int col = wn*32 + nt*8 + 2*tig;
            #pragma unroll
            for (int half = 0; half < 2; half++) {
                int lrow = wm*32 + mt*16 + gid + half*8;
                float vx = fmaxf(acc[mt][nt][half*2 + 0] + bl[col],     0.f);
                float vy = fmaxf(acc[mt][nt][half*2 + 1] + bl[col + 1], 0.f);
                SP2[lrow*SPP + (col >> 1)] = bpack2(vx, vy);
            }
        }
    __syncthreads();

    // ---------------- phase 2: GX = SP @ W_ih^T + b_ih (3 N-subtiles) -------
    auto issue_copyB = [&](int idx) {   // idx = nt*4 + kc
        int nt = idx >> 2, kc = idx & 3;
        const uint32_t sb = smem_b + (uint32_t)((idx & 1) * STGP + A128P) * 8u;
        #pragma unroll
        for (int h = 0; h < 2; h++) {
            int i = tid + h*512;
            int row = i >> 3, seg = i & 7;
            uint32_t soff = (uint32_t)(row * PR + seg * 2) * 8u;
            CP_ASYNC16(sb + soff, g_Wih2 + (size_t)(nt*128 + row)*64 + kc*16 + seg*2, 16);
        }
        CP_COMMIT();
    };

    issue_copyB(0);
    for (int nt3 = 0; nt3 < 3; nt3++) {
        #pragma unroll
        for (int i = 0; i < 2; i++)
            #pragma unroll
            for (int j = 0; j < 4; j++)
                #pragma unroll
                for (int k = 0; k < 4; k++) acc[i][j][k] = 0.f;

        for (int kc = 0; kc < 4; kc++) {
            int idx = nt3*4 + kc;
            if (idx + 1 < 12) { issue_copyB(idx + 1); CP_WAIT1(); } else { CP_WAIT0(); }
            __syncthreads();
            const uint2* B2 = sm2 + (idx & 1) * STGP + A128P;

            #pragma unroll
            for (int ks = 0; ks < 2; ks++) {
                const int ka = kc*8 + ks*4 + tig;   // SP pair index (full 64)
                const int kb = ks*8 + tig;          // wait—see below
                // SP pair index: k element = kc*32 + ks*16 + tig*2 -> pair = kc*16 + ks*8 + tig
                const int kap = kc*16 + ks*8 + tig;
                uint32_t afh[2][4], afl[2][4];
                #pragma unroll
                for (int mt = 0; mt < 2; mt++)
                    LD_A(afh[mt], afl[mt], SP2, SPP, wm*32 + mt*16 + gid, kap);
                #pragma unroll
                for (int nt = 0; nt < 4; nt++) {
                    int cb = wn*32 + nt*8 + gid;
                    uint32_t bfh[2], bfl[2];
                    LD_B(bfh, bfl, B2, PR, cb, kb);
                    #pragma unroll
                    for (int mt = 0; mt < 2; mt++) {
                        MMA_BF16(acc[mt][nt], afh[mt], bfh);
                        MMA_BF16(acc[mt][nt], afh[mt], bfl);
                        MMA_BF16(acc[mt][nt], afl[mt], bfh);
                    }
                }
                (void)ka;
            }
            __syncthreads();
        }

        #pragma unroll
        for (int mt = 0; mt < 2; mt++)
            #pragma unroll
            for (int nt = 0; nt < 4; nt++) {
                int col = nt3*128 + wn*32 + nt*8 + 2*tig;
                #pragma unroll
                for (int half = 0; half < 2; half++) {
                    int row = bm + wm*32 + mt*16 + gid + half*8;
                    float2 o;
                    o.x = acc[mt][nt][half*2 + 0] + b_ih[col];
                    o.y = acc[mt][nt][half*2 + 1] + b_ih[col + 1];
                    *(float2*)(g_GX + (size_t)row*384 + col) = o;
                }
            }
    }
}

// ======================= head GEMM + fused cls ===============================
#define HEAD_SMEM (2*STGP*8)           /* 81920 B */
__global__ void __launch_bounds__(512, 1) head_kernel(
    const float* __restrict__ w2, const float* __restrict__ b2,
    float* __restrict__ recon, float* __restrict__ clsOut)
{
    extern __shared__ uint2 sm2[];
    uint32_t smem_b;
    asm("{ .reg .u64 t; cvta.to.shared.u64 t, %1; cvt.u32.u64 %0, t; }"
        : "=r"(smem_b) : "l"(sm2));

    const int tid  = threadIdx.x;
    const int lane = tid & 31;
    const int w    = tid >> 5;
    const int gid  = lane >> 2;
    const int tig  = lane & 3;
    const int wm   = w >> 2;
    const int wn   = w & 3;
    const int bm   = blockIdx.x * 128;

    float acc[2][4][4];
    #pragma unroll
    for (int i = 0; i < 2; i++)
        #pragma unroll
        for (int j = 0; j < 4; j++)
            #pragma unroll
            for (int k = 0; k < 4; k++) acc[i][j][k] = 0.f;

    auto issue_copy = [&](int kc) {
        const uint32_t sb = smem_b + (uint32_t)((kc & 1) * STGP) * 8u;
        #pragma unroll
        for (int h = 0; h < 2; h++) {
            int i = tid + h*512;
            int row = i >> 3, seg = i & 7;
            uint32_t soff = (uint32_t)(row * PR + seg * 2) * 8u;
            CP_ASYNC16(sb + soff, g_HS2 + (size_t)(bm + row)*64 + kc*16 + seg*2, 16);
            CP_ASYNC16(sb + (uint32_t)A128P*8u + soff,
                       g_Whd2 + (size_t)min(row, 95)*64 + kc*16 + seg*2,
                       (row < 96) ? 16 : 0);
        }
        CP_COMMIT();
    };

    issue_copy(0);
    for (int kc = 0; kc < 4; kc++) {
        if (kc + 1 < 4) { issue_copy(kc + 1); CP_WAIT1(); } else { CP_WAIT0(); }
        __syncthreads();
        const uint2* A2 = sm2 + (kc & 1) * STGP;
        const uint2* B2 = A2 + A128P;
        #pragma unroll
        for (int ks = 0; ks < 2; ks++) {
            const int kb = ks*8 + tig;
            uint32_t afh[2][4], afl[2][4];
            #pragma unroll
            for (int mt = 0; mt < 2; mt++)
                LD_A(afh[mt], afl[mt], A2, PR, wm*32 + mt*16 + gid, kb);
            #pragma unroll
            for (int nt = 0; nt < 4; nt++) {
                int cb = wn*32 + nt*8 + gid;
                uint32_t bfh[2], bfl[2];
                LD_B(bfh, bfl, B2, PR, cb, kb);
                #pragma unroll
                for (int mt = 0; mt < 2; mt++) {
                    MMA_BF16(acc[mt][nt], afh[mt], bfh);
                    MMA_BF16(acc[mt][nt], afh[mt], bfl);
                    MMA_BF16(acc[mt][nt], afl[mt], bfh);
                }
            }
        }
        __syncthreads();
    }

    float* c1s = (float*)sm2;     // alias stage region (GEMM done)
    #pragma unroll
    for (int mt = 0; mt < 2; mt++)
        #pragma unroll
        for (int nt = 0; nt < 4; nt++) {
            int col = wn*32 + nt*8 + 2*tig;
            if (col >= 96) continue;
            #pragma unroll
            for (int half = 0; half < 2; half++) {
                int row = bm + wm*32 + mt*16 + gid + half*8;
                float2 o;
                o.x = acc[mt][nt][half*2 + 0] + g_bh[col];
                o.y = acc[mt][nt][half*2 + 1] + g_bh[col + 1];
                if (col < 32) {
                    *(float2*)(recon + (size_t)row*32 + col) = o;
                } else {
                    int lrow = row - bm;
                    c1s[lrow*C1S + col - 32]     = fmaxf(o.x, 0.f);
                    c1s[lrow*C1S + col - 32 + 1] = fmaxf(o.y, 0.f);
                }
            }
        }
    __syncthreads();
    #pragma unroll
    for (int rr = 0; rr < 8; rr++) {
        int lrow = w*8 + rr;
        float s = c1s[lrow*C1S + lane]      * w2[lane]
                + c1s[lrow*C1S + 32 + lane] * w2[32 + lane];
        #pragma unroll
        for (int o = 16; o; o >>= 1) s += __shfl_xor_sync(0xffffffffu, s, o);
        if (lane == 0) clsOut[bm + lrow] = sigmoidf_(s + b2[0]);
    }
}

// ======================= fused GH GEMM + register GRU (t>=1) =================
#define A64P  (64*PR)                  /* 1280 uint2 */
#define B384P (384*PR)                 /* 7680 uint2 */
#define GSTG  (A64P + B384P)           /* 8960 uint2 */
#define GH_SMEM (2*GSTG*8)             /* 143360 B */

__global__ void __launch_bounds__(512, 1) ghgru_kernel(
    int t, const float* __restrict__ b_hh)
{
    extern __shared__ uint2 sm2[];
    uint32_t smem_b;
    asm("{ .reg .u64 t; cvta.to.shared.u64 t, %1; cvt.u32.u64 %0, t; }"
        : "=r"(smem_b) : "l"(sm2));

    const int tid  = threadIdx.x;
    const int lane = tid & 31;
    const int w    = tid >> 5;
    const int gid  = lane >> 2;
    const int tig  = lane & 3;
    const int wm   = w >> 2;
    const int wn   = w & 3;
    const int bm   = blockIdx.x * 64;

    float acc[3][4][4];
    #pragma unroll
    for (int g = 0; g < 3; g++)
        #pragma unroll
        for (int j = 0; j < 4; j++)
            #pragma unroll
            for (int k = 0; k < 4; k++) acc[g][j][k] = 0.f;

    auto issue_copy = [&](int kc) {
        const uint32_t sb = smem_b + (uint32_t)((kc & 1) * GSTG) * 8u;
        // A: 64 rows x 8 segs = 512 -> 1/thread
        {
            int row = tid >> 3, seg = tid & 7;
            uint32_t soff = (uint32_t)(row * PR + seg * 2) * 8u;
            int grow = bm + row;
            CP_ASYNC16(sb + soff,
                       g_H2 + (size_t)min(grow, NNODES - 1)*64 + kc*16 + seg*2,
                       (grow < NNODES) ? 16 : 0);
        }
        // B: 384 rows x 8 segs = 3072 -> 6/thread
        #pragma unroll
        for (int h = 0; h < 6; h++) {
            int i = tid + h*512;
            int row = i >> 3, seg = i & 7;
            uint32_t soff = (uint32_t)(A64P + row * PR + seg * 2) * 8u;
            CP_ASYNC16(sb + soff, g_Whh2 + (size_t)row*64 + kc*16 + seg*2, 16);
        }
        CP_COMMIT();
    };

    issue_copy(0);
    for (int kc = 0; kc < 4; kc++) {
        if (kc + 1 < 4) { issue_copy(kc + 1); CP_WAIT1(); } else { CP_WAIT0(); }
        __syncthreads();
        const uint2* A2 = sm2 + (kc & 1) * GSTG;
        const uint2* B2 = A2 + A64P;
        #pragma unroll
        for (int ks = 0; ks < 2; ks++) {
            const int kb = ks*8 + tig;
            uint32_t afh[4], afl[4];
            LD_A(afh, afl, A2, PR, wm*16 + gid, kb);
            #pragma unroll
            for (int g = 0; g < 3; g++) {
                #pragma unroll
                for (int nt = 0; nt < 4; nt++) {
                    int cb = g*128 + wn*32 + nt*8 + gid;
                    uint32_t bfh[2], bfl[2];
                    LD_B(bfh, bfl, B2, PR, cb, kb);
                    MMA_BF16(acc[g][nt], afh, bfh);
                    MMA_BF16(acc[g][nt], afh, bfl);
                    MMA_BF16(acc[g][nt], afl, bfh);
                }
            }
        }
        __syncthreads();
    }

    #pragma unroll
    for (int nt = 0; nt < 4; nt++) {
        int col = wn*32 + nt*8 + 2*tig;
        float2 bhr = *(const float2*)(b_hh + col);
        float2 bhz = *(const float2*)(b_hh + 128 + col);
        float2 bhn = *(const float2*)(b_hh + 256 + col);
        #pragma unroll
        for (int half = 0; half < 2; half++) {
            int node = bm + wm*16 + gid + half*8;
            if (node >= NNODES) continue;
            size_t m = (size_t)node*8 + t;
            float2 gxr = *(const float2*)(g_GX + m*384 + col);
            float2 gxz = *(const float2*)(g_GX + m*384 + 128 + col);
            float2 gxn = *(const float2*)(g_GX + m*384 + 256 + col);
            float2 h   = bunpack2(g_H2[(size_t)node*64 + (col >> 1)]);
            float ghr0 = acc[0][nt][half*2+0] + bhr.x, ghr1 = acc[0][nt][half*2+1] + bhr.y;
            float ghz0 = acc[1][nt][half*2+0] + bhz.x, ghz1 = acc[1][nt][half*2+1] + bhz.y;
            float ghn0 = acc[2][nt][half*2+0] + bhn.x, ghn1 = acc[2][nt][half*2+1] + bhn.y;
            float r0 = sigmoidf_(gxr.x + ghr0), r1 = sigmoidf_(gxr.y + ghr1);
            float z0 = sigmoidf_(gxz.x + ghz0), z1 = sigmoidf_(gxz.y + ghz1);
            float n0 = tanhf(gxn.x + r0*ghn0),  n1 = tanhf(gxn.y + r1*ghn1);
            float hn0 = (1.f - z0)*n0 + z0*h.x;
            float hn1 = (1.f - z1)*n1 + z1*h.y;
            uint2 v = bpack2(hn0, hn1);
            g_H2 [(size_t)node*64 + (col >> 1)] = v;
            g_HS2[m*64 + (col >> 1)]            = v;
        }
    }
}

// ======================= launch ==============================================
extern "C" void kernel_launch(void* const* d_in, const int* in_sizes, int n_in,
                              void* d_out, int out_size)
{
    const float* x     = (const float*)d_in[0];
    const void*  ei    = d_in[1];
    const float* Wl    = (const float*)d_in[2];
    const float* bl    = (const float*)d_in[3];
    const float* Wr    = (const float*)d_in[4];
    const float* W_ih  = (const float*)d_in[5];
    const float* b_ih  = (const float*)d_in[6];
    const float* W_hh  = (const float*)d_in[7];
    const float* b_hh  = (const float*)d_in[8];
    const float* W_rec = (const float*)d_in[9];
    const float* b_rec = (const float*)d_in[10];
    const float* W_c1  = (const float*)d_in[11];
    const float* b_c1  = (const float*)d_in[12];
    const float* W_c2  = (const float*)d_in[13];
    const float* b_c2  = (const float*)d_in[14];

    float* out      = (float*)d_out;
    float* outRecon = out;
    float* outCls   = out + (size_t)MROWS * COUT;

    cudaFuncSetAttribute(spgx_kernel,  cudaFuncAttributeMaxDynamicSharedMemorySize, SPX_SMEM);
    cudaFuncSetAttribute(head_kernel,  cudaFuncAttributeMaxDynamicSharedMemorySize, HEAD_SMEM);
    cudaFuncSetAttribute(ghgru_kernel, cudaFuncAttributeMaxDynamicSharedMemorySize, GH_SMEM);

    // graph + weight prep
    detect_kernel<<<1, 1>>>(ei);
    convert_kernel<<<(EDGES + 255)/256, 256>>>(ei);
    zero_kernel<<<256, 256>>>();
    wcat2_kernel<<<(128*32 + 255)/256, 256>>>(Wl, Wr);
    wih2_kernel<<<(384*64 + 255)/256, 256>>>(W_ih);
    whh2_kernel<<<(384*64 + 255)/256, 256>>>(W_hh);
    whd2_kernel<<<(96*64 + 255)/256, 256>>>(W_rec, b_rec, W_c1, b_c1);
    count_kernel<<<(EDGES + 255)/256, 256>>>();
    scan_kernel<<<1, 1024>>>();
    fill_kernel<<<(EDGES + 255)/256, 256>>>();
    gather_kernel<<<NNODES, 256>>>(x);

    // fused SP+GX
    spgx_kernel<<<MROWS/128, 512, SPX_SMEM>>>(bl, b_ih);

    // recurrence
    gru0_kernel<<<(NNODES*HH + 255)/256, 256>>>(b_hh);
    for (int t = 1; t < TT; t++)
        ghgru_kernel<<<(NNODES + 63)/64, 512, GH_SMEM>>>(t, b_hh);

    // heads
    head_kernel<<<MROWS/128, 512, HEAD_SMEM>>>(W_c2, b_c2, outRecon, outCls);
}

// round 15
// speedup vs baseline: 1.0672x; 1.0672x over previous
#include <cuda_runtime.h>
#include <cuda_bf16.h>
#include <math.h>
#include <stdint.h>

#define NNODES 50000
#define TT 8
#define HH 128
#define COUT 32
#define EDGES 800000
#define MROWS 400000

typedef unsigned short ushort_t;

// ======================= scratch (device globals) ============================
__device__ int   g_is64;
__device__ int   g_src[EDGES];
__device__ int   g_dst[EDGES];
__device__ int   g_cnt[NNODES];
__device__ int   g_off[NNODES];
__device__ int   g_cur[NNODES];
__device__ int   g_adj[EDGES];
__device__ float g_GX [(size_t)MROWS*3*HH];    // [m, 384] fp32 (t>=1 rows only)
__device__ float g_bh [96];
// packed-bf16 hi/lo operand arrays
__device__ ushort_t g_AXhi[(size_t)MROWS*64],   g_AXlo[(size_t)MROWS*64];
__device__ ushort_t g_Wcathi[128*64],           g_Wcatlo[128*64];
__device__ ushort_t g_Wihhi[384*128],           g_Wihlo[384*128];
__device__ ushort_t g_Whhhi[384*128],           g_Whhlo[384*128];
__device__ ushort_t g_Whdhi[96*128],            g_Whdlo[96*128];
__device__ ushort_t g_HShi[(size_t)MROWS*128],  g_HSlo[(size_t)MROWS*128];

// ======================= helpers =============================================
__device__ __forceinline__ void bsplit1(float v, ushort_t& h, ushort_t& l) {
    __nv_bfloat16 hb = __float2bfloat16_rn(v);
    __nv_bfloat16 lb = __float2bfloat16_rn(v - __bfloat162float(hb));
    h = __bfloat16_as_ushort(hb); l = __bfloat16_as_ushort(lb);
}
__device__ __forceinline__ void bsplit2(float v0, float v1, uint32_t& hi, uint32_t& lo) {
    ushort_t h0, l0, h1, l1;
    bsplit1(v0, h0, l0); bsplit1(v1, h1, l1);
    hi = ((uint32_t)h1 << 16) | h0;
    lo = ((uint32_t)l1 << 16) | l0;
}
__device__ __forceinline__ float2 bjoin2(uint32_t hi, uint32_t lo) {
    float2 r;
    r.x = __bfloat162float(__ushort_as_bfloat16((ushort_t)(hi & 0xffff)))
        + __bfloat162float(__ushort_as_bfloat16((ushort_t)(lo & 0xffff)));
    r.y = __bfloat162float(__ushort_as_bfloat16((ushort_t)(hi >> 16)))
        + __bfloat162float(__ushort_as_bfloat16((ushort_t)(lo >> 16)));
    return r;
}
#define MMA_BF16(C, Af, Bf) \
    asm volatile( \
        "mma.sync.aligned.m16n8k16.row.col.f32.bf16.bf16.f32 " \
        "{%0,%1,%2,%3}, {%4,%5,%6,%7}, {%8,%9}, {%0,%1,%2,%3};" \
        : "+f"((C)[0]), "+f"((C)[1]), "+f"((C)[2]), "+f"((C)[3]) \
        : "r"((Af)[0]), "r"((Af)[1]), "r"((Af)[2]), "r"((Af)[3]), \
          "r"((Bf)[0]), "r"((Bf)[1]))
#define CP_ASYNC16(dst, src, sz) \
    asm volatile("cp.async.ca.shared.global [%0], [%1], 16, %2;" \
                 :: "r"(dst), "l"(src), "r"(sz))
#define CP_COMMIT() asm volatile("cp.async.commit_group;" ::: "memory")
#define CP_WAIT1()  asm volatile("cp.async.wait_group 1;" ::: "memory")
#define CP_WAIT0()  asm volatile("cp.async.wait_group 0;" ::: "memory")
__device__ __forceinline__ float sigmoidf_(float v) { return 1.f / (1.f + expf(-v)); }

#define LD_A4(af, P, S2, r0, kk) do { \
    (af)[0] = *(const uint32_t*)&(P)[ (r0)    *(S2) + (kk)    ]; \
    (af)[1] = *(const uint32_t*)&(P)[((r0)+8) *(S2) + (kk)    ]; \
    (af)[2] = *(const uint32_t*)&(P)[ (r0)    *(S2) + (kk) + 8]; \
    (af)[3] = *(const uint32_t*)&(P)[((r0)+8) *(S2) + (kk) + 8]; \
} while (0)
#define LD_B2(bf, P, S2, cb, kk) do { \
    (bf)[0] = *(const uint32_t*)&(P)[(cb)*(S2) + (kk)    ]; \
    (bf)[1] = *(const uint32_t*)&(P)[(cb)*(S2) + (kk) + 8]; \
} while (0)

// ======================= edge prep ===========================================
__global__ void detect_kernel(const void* ei) {
    const unsigned long long* p = (const unsigned long long*)ei;
    int is64 = 1;
    for (int i = 0; i < 1024; i++)
        if ((p[i] >> 32) != 0ull) { is64 = 0; break; }
    g_is64 = is64;
}
__global__ void zero_kernel() {
    int idx = blockIdx.x * blockDim.x + threadIdx.x;
    int stride = gridDim.x * blockDim.x;
    for (int i = idx; i < NNODES; i += stride) g_cnt[i] = 0;
}
__global__ void convcount_kernel(const void* ei) {
    int e = blockIdx.x * blockDim.x + threadIdx.x;
    if (e >= EDGES) return;
    int s, d;
    if (g_is64) {
        const long long* p = (const long long*)ei;
        s = (int)p[e]; d = (int)p[EDGES + e];
    } else {
        const int* p = (const int*)ei;
        s = p[e]; d = p[EDGES + e];
    }
    s = min(max(s, 0), NNODES - 1);
    d = min(max(d, 0), NNODES - 1);
    g_src[e] = s;
    g_dst[e] = d;
    atomicAdd(&g_cnt[d], 1);
}
__global__ void scan_kernel() {
    __shared__ int partial[1024];
    const int CH = (NNODES + 1023) / 1024;
    int t = threadIdx.x;
    int begin = t * CH;
    int end   = min(begin + CH, NNODES);
    int s = 0;
    for (int i = begin; i < end; i++) s += g_cnt[i];
    partial[t] = s;
    __syncthreads();
    #pragma unroll
    for (int d = 1; d < 1024; d <<= 1) {
        int v = (t >= d) ? partial[t - d] : 0;
        __syncthreads();
        partial[t] += v;
        __syncthreads();
    }
    int off = partial[t] - s;
    for (int i = begin; i < end; i++) {
        g_off[i] = off;
        g_cur[i] = off;
        off += g_cnt[i];
    }
}
__global__ void fill_kernel() {
    int e = blockIdx.x * blockDim.x + threadIdx.x;
    if (e >= EDGES) return;
    int pos = atomicAdd(&g_cur[g_dst[e]], 1);
    g_adj[pos] = g_src[e];
}
__global__ void __launch_bounds__(256) gather_kernel(const float* __restrict__ x) {
    int n   = blockIdx.x;
    int idx = threadIdx.x;
    int beg = g_off[n];
    int cnt = g_cnt[n];
    float s = 0.f;
    for (int p = beg; p < beg + cnt; p++) {
        int src = g_adj[p];
        s += x[(size_t)src * 256 + idx];
    }
    float dg = fmaxf((float)cnt, 1.f);
    int t = idx >> 5, c = idx & 31;
    size_t m = (size_t)n * 8 + t;
    ushort_t h, l;
    bsplit1(s / dg, h, l);
    g_AXhi[m*64 + c] = h;      g_AXlo[m*64 + c] = l;
    bsplit1(x[(size_t)n * 256 + idx], h, l);
    g_AXhi[m*64 + 32 + c] = h; g_AXlo[m*64 + 32 + c] = l;
}
// weight conversions
__global__ void wcat2_kernel(const float* __restrict__ Wl, const float* __restrict__ Wr) {
    int idx = blockIdx.x * blockDim.x + threadIdx.x;
    if (idx >= 128*64) return;
    int j = idx >> 6, c = idx & 63;
    float v = (c < 32) ? Wl[j*32 + c] : Wr[j*32 + (c-32)];
    bsplit1(v, g_Wcathi[idx], g_Wcatlo[idx]);
}
__global__ void wih2_kernel(const float* __restrict__ W_ih) {
    int idx = blockIdx.x * blockDim.x + threadIdx.x;
    if (idx >= 384*128) return;
    bsplit1(W_ih[idx], g_Wihhi[idx], g_Wihlo[idx]);
}
__global__ void whh2_kernel(const float* __restrict__ W_hh) {
    int idx = blockIdx.x * blockDim.x + threadIdx.x;
    if (idx >= 384*128) return;
    bsplit1(W_hh[idx], g_Whhhi[idx], g_Whhlo[idx]);
}
__global__ void whd2_kernel(const float* __restrict__ W_rec, const float* __restrict__ b_rec,
                            const float* __restrict__ W_c1,  const float* __restrict__ b_c1) {
    int idx = blockIdx.x * blockDim.x + threadIdx.x;
    if (idx < 96*128) {
        int r = idx >> 7, k = idx & 127;
        float v = (r < 32) ? W_rec[r*128 + k] : W_c1[(r-32)*128 + k];
        bsplit1(v, g_Whdhi[idx], g_Whdlo[idx]);
    }
    if (idx < 96) g_bh[idx] = (idx < 32) ? b_rec[idx] : b_c1[idx - 32];
}

// ======================= tiling constants ====================================
#define SRW2 40                       /* ushort stride for 32-k chunk rows */
#define A128 (128*SRW2)               /* 5120 ushorts */
#define STG2 (4*A128)                 /* Ahi,Alo,Bhi,Blo = 20480 ushorts */
#define C1S  72

// ======================= fused SP+GX(+t0 GRU) kernel =========================
#define SPX_ST2  136
#define SPHI_OFF (2*STG2)                       /* 40960 ushorts */
#define SPLO_OFF (SPHI_OFF + 128*SPX_ST2)       /* 58368 */
#define GX0_OFF  (SPLO_OFF + 128*SPX_ST2)       /* 75776 ushorts -> float buf  */
#define SPX_SMEM (GX0_OFF*2 + 16*392*4)         /* 151552 + 25088 = 176640 B */

__global__ void __launch_bounds__(512, 1) spgx_kernel(
    const float* __restrict__ bl, const float* __restrict__ b_ih,
    const float* __restrict__ b_hh)
{
    extern __shared__ ushort_t smem[];
    uint32_t smem_b;
    asm("{ .reg .u64 t; cvta.to.shared.u64 t, %1; cvt.u32.u64 %0, t; }"
        : "=r"(smem_b) : "l"(smem));

    const int tid  = threadIdx.x;
    const int lane = tid & 31;
    const int w    = tid >> 5;
    const int gid  = lane >> 2;
    const int tig  = lane & 3;
    const int wm   = w >> 2;
    const int wn   = w & 3;
    const int bm   = blockIdx.x * 128;
    ushort_t* SPhi = smem + SPHI_OFF;
    ushort_t* SPlo = smem + SPLO_OFF;
    float*    gx0  = (float*)(smem + GX0_OFF);   // [16][392] t=0 gate stash

    float acc[2][4][4];
    #pragma unroll
    for (int i = 0; i < 2; i++)
        #pragma unroll
        for (int j = 0; j < 4; j++)
            #pragma unroll
            for (int k = 0; k < 4; k++) acc[i][j][k] = 0.f;

    // ---------------- phase 1: SP = relu(AX @ Wcat^T + bl) ----------------
    auto issue_copy1 = [&](int kc) {
        const uint32_t sb = smem_b + (uint32_t)((kc & 1) * STG2) * 2u;
        int row = tid >> 2, seg = tid & 3;
        uint32_t soff = (uint32_t)(row * SRW2 + seg * 8) * 2u;
        size_t goff = (size_t)(bm + row) * 64 + kc * 32 + seg * 8;
        size_t woff = (size_t)row * 64 + kc * 32 + seg * 8;
        CP_ASYNC16(sb + soff,                    g_AXhi  + goff, 16);
        CP_ASYNC16(sb + (uint32_t)A128*2 + soff, g_AXlo  + goff, 16);
        CP_ASYNC16(sb + (uint32_t)(2*A128)*2 + soff, g_Wcathi + woff, 16);
        CP_ASYNC16(sb + (uint32_t)(3*A128)*2 + soff, g_Wcatlo + woff, 16);
        CP_COMMIT();
    };

    issue_copy1(0);
    for (int kc = 0; kc < 2; kc++) {
        if (kc == 0) { issue_copy1(1); CP_WAIT1(); } else { CP_WAIT0(); }
        __syncthreads();
        const ushort_t* Ahi = smem + (kc & 1) * STG2;
        const ushort_t* Alo = Ahi + A128;
        const ushort_t* Bhi = Ahi + 2*A128;
        const ushort_t* Blo = Ahi + 3*A128;
        #pragma unroll
        for (int ks = 0; ks < 2; ks++) {
            const int kk = ks*16 + tig*2;
            uint32_t afh[2][4], afl[2][4];
            #pragma unroll
            for (int mt = 0; mt < 2; mt++) {
                LD_A4(afh[mt], Ahi, SRW2, wm*32 + mt*16 + gid, kk);
                LD_A4(afl[mt], Alo, SRW2, wm*32 + mt*16 + gid, kk);
            }
            #pragma unroll
            for (int nt = 0; nt < 4; nt++) {
                int cb = wn*32 + nt*8 + gid;
                uint32_t bfh[2], bfl[2];
                LD_B2(bfh, Bhi, SRW2, cb, kk);
                LD_B2(bfl, Blo, SRW2, cb, kk);
                #pragma unroll
                for (int mt = 0; mt < 2; mt++) {
                    MMA_BF16(acc[mt][nt], afh[mt], bfh);
                    MMA_BF16(acc[mt][nt], afh[mt], bfl);
                    MMA_BF16(acc[mt][nt], afl[mt], bfh);
                }
            }
        }
        __syncthreads();
    }
    // stage relu(SP) split into smem hi/lo
    #pragma unroll
    for (int mt = 0; mt < 2; mt++)
        #pragma unroll
        for (int nt = 0; nt < 4; nt++) {
            int col = wn*32 + nt*8 + 2*tig;
            #pragma unroll
            for (int half = 0; half < 2; half++) {
                int lrow = wm*32 + mt*16 + gid + half*8;
                float vx = fmaxf(acc[mt][nt][half*2 + 0] + bl[col],     0.f);
                float vy = fmaxf(acc[mt][nt][half*2 + 1] + bl[col + 1], 0.f);
                uint32_t hi, lo;
                bsplit2(vx, vy, hi, lo);
                *(uint32_t*)&SPhi[lrow*SPX_ST2 + col] = hi;
                *(uint32_t*)&SPlo[lrow*SPX_ST2 + col] = lo;
            }
        }
    __syncthreads();

    // ---------------- phase 2: GX = SP @ W_ih^T + b_ih (3 N-subtiles) -------
    auto issue_copyB = [&](int idx) {   // idx = nt*4 + kc
        int nt = idx >> 2, kc = idx & 3;
        const uint32_t sb = smem_b + (uint32_t)((idx & 1) * STG2) * 2u;
        int row = tid >> 2, seg = tid & 3;
        uint32_t soff = (uint32_t)(row * SRW2 + seg * 8) * 2u;
        size_t goff = (size_t)(nt*128 + row) * 128 + kc * 32 + seg * 8;
        CP_ASYNC16(sb + (uint32_t)(2*A128)*2 + soff, g_Wihhi + goff, 16);
        CP_ASYNC16(sb + (uint32_t)(3*A128)*2 + soff, g_Wihlo + goff, 16);
        CP_COMMIT();
    };

    issue_copyB(0);
    for (int nt3 = 0; nt3 < 3; nt3++) {
        #pragma unroll
        for (int i = 0; i < 2; i++)
            #pragma unroll
            for (int j = 0; j < 4; j++)
                #pragma unroll
                for (int k = 0; k < 4; k++) acc[i][j][k] = 0.f;

        for (int kc = 0; kc < 4; kc++) {
            int idx = nt3*4 + kc;
            if (idx + 1 < 12) { issue_copyB(idx + 1); CP_WAIT1(); } else { CP_WAIT0(); }
            __syncthreads();
            const ushort_t* Bhi = smem + (idx & 1) * STG2 + 2*A128;
            const ushort_t* Blo = Bhi + A128;

            #pragma unroll
            for (int ks = 0; ks < 2; ks++) {
                const int ka = kc*32 + ks*16 + tig*2;
                const int kb = ks*16 + tig*2;
                uint32_t afh[2][4], afl[2][4];
                #pragma unroll
                for (int mt = 0; mt < 2; mt++) {
                    LD_A4(afh[mt], SPhi, SPX_ST2, wm*32 + mt*16 + gid, ka);
                    LD_A4(afl[mt], SPlo, SPX_ST2, wm*32 + mt*16 + gid, ka);
                }
                #pragma unroll
                for (int nt = 0; nt < 4; nt++) {
                    int cb = wn*32 + nt*8 + gid;
                    uint32_t bfh[2], bfl[2];
                    LD_B2(bfh, Bhi, SRW2, cb, kb);
                    LD_B2(bfl, Blo, SRW2, cb, kb);
                    #pragma unroll
                    for (int mt = 0; mt < 2; mt++) {
                        MMA_BF16(acc[mt][nt], afh[mt], bfh);
                        MMA_BF16(acc[mt][nt], afh[mt], bfl);
                        MMA_BF16(acc[mt][nt], afl[mt], bfh);
                    }
                }
            }
            __syncthreads();
        }

        // write GX subtile (t>=1 rows); stash t=0 rows' gates in smem
        #pragma unroll
        for (int mt = 0; mt < 2; mt++)
            #pragma unroll
            for (int nt = 0; nt < 4; nt++) {
                int col = nt3*128 + wn*32 + nt*8 + 2*tig;
                #pragma unroll
                for (int half = 0; half < 2; half++) {
                    int lrow = wm*32 + mt*16 + gid + half*8;
                    int row  = bm + lrow;
                    float ox = acc[mt][nt][half*2 + 0] + b_ih[col];
                    float oy = acc[mt][nt][half*2 + 1] + b_ih[col + 1];
                    if ((lrow & 7) == 0) {
                        int rr = lrow >> 3;
                        gx0[rr*392 + col]     = ox;
                        gx0[rr*392 + col + 1] = oy;
                    } else {
                        float2 o = make_float2(ox, oy);
                        *(float2*)(g_GX + (size_t)row*384 + col) = o;
                    }
                }
            }
    }
    __syncthreads();

    // ---------------- t=0 GRU (gh = b_hh), write HS ----------------
    for (int e = tid; e < 16*64; e += 512) {
        int rr = e >> 6;
        int j  = (e & 63) * 2;
        size_t m = (size_t)(bm + rr*8);
        float r0 = sigmoidf_(gx0[rr*392 + j]       + b_hh[j]);
        float r1 = sigmoidf_(gx0[rr*392 + j + 1]   + b_hh[j + 1]);
        float z0 = sigmoidf_(gx0[rr*392 + 128 + j]     + b_hh[128 + j]);
        float z1 = sigmoidf_(gx0[rr*392 + 128 + j + 1] + b_hh[128 + j + 1]);
        float n0 = tanhf(gx0[rr*392 + 256 + j]     + r0 * b_hh[256 + j]);
        float n1 = tanhf(gx0[rr*392 + 256 + j + 1] + r1 * b_hh[256 + j + 1]);
        float h0 = (1.f - z0)*n0;
        float h1 = (1.f - z1)*n1;
        uint32_t hi, lo;
        bsplit2(h0, h1, hi, lo);
        *(uint32_t*)&g_HShi[m*128 + j] = hi;
        *(uint32_t*)&g_HSlo[m*128 + j] = lo;
    }
}

// ======================= head GEMM + fused cls ===============================
#define HEAD_SMEM (2*STG2*2)          /* 81920 B */
__global__ void __launch_bounds__(512, 1) head_kernel(
    const float* __restrict__ w2, const float* __restrict__ b2,
    float* __restrict__ recon, float* __restrict__ clsOut)
{
    extern __shared__ ushort_t smem[];
    uint32_t smem_b;
    asm("{ .reg .u64 t; cvta.to.shared.u64 t, %1; cvt.u32.u64 %0, t; }"
        : "=r"(smem_b) : "l"(smem));

    const int tid  = threadIdx.x;
    const int lane = tid & 31;
    const int w    = tid >> 5;
    const int gid  = lane >> 2;
    const int tig  = lane & 3;
    const int wm   = w >> 2;
    const int wn   = w & 3;
    const int bm   = blockIdx.x * 128;

    float acc[2][4][4];
    #pragma unroll
    for (int i = 0; i < 2; i++)
        #pragma unroll
        for (int j = 0; j < 4; j++)
            #pragma unroll
            for (int k = 0; k < 4; k++) acc[i][j][k] = 0.f;

    auto issue_copy = [&](int kc) {
        const uint32_t sb = smem_b + (uint32_t)((kc & 1) * STG2) * 2u;
        int row = tid >> 2, seg = tid & 3;
        uint32_t soff = (uint32_t)(row * SRW2 + seg * 8) * 2u;
        size_t aoff = (size_t)(bm + row) * 128 + kc * 32 + seg * 8;
        size_t woff = (size_t)min(row, 95) * 128 + kc * 32 + seg * 8;
        int wsz = (row < 96) ? 16 : 0;
        CP_ASYNC16(sb + soff,                        g_HShi + aoff, 16);
        CP_ASYNC16(sb + (uint32_t)A128*2 + soff,     g_HSlo + aoff, 16);
        CP_ASYNC16(sb + (uint32_t)(2*A128)*2 + soff, g_Whdhi + woff, wsz);
        CP_ASYNC16(sb + (uint32_t)(3*A128)*2 + soff, g_Whdlo + woff, wsz);
        CP_COMMIT();
    };

    issue_copy(0);
    for (int kc = 0; kc < 4; kc++) {
        if (kc + 1 < 4) { issue_copy(kc + 1); CP_WAIT1(); } else { CP_WAIT0(); }
        __syncthreads();
        const ushort_t* Ahi = smem + (kc & 1) * STG2;
        const ushort_t* Alo = Ahi + A128;
        const ushort_t* Bhi = Ahi + 2*A128;
        const ushort_t* Blo = Ahi + 3*A128;
        #pragma unroll
        for (int ks = 0; ks < 2; ks++) {
            const int kk = ks*16 + tig*2;
            uint32_t afh[2][4], afl[2][4];
            #pragma unroll
            for (int mt = 0; mt < 2; mt++) {
                LD_A4(afh[mt], Ahi, SRW2, wm*32 + mt*16 + gid, kk);
                LD_A4(afl[mt], Alo, SRW2, wm*32 + mt*16 + gid, kk);
            }
            #pragma unroll
            for (int nt = 0; nt < 4; nt++) {
                int cb = wn*32 + nt*8 + gid;
                uint32_t bfh[2], bfl[2];
                LD_B2(bfh, Bhi, SRW2, cb, kk);
                LD_B2(bfl, Blo, SRW2, cb, kk);
                #pragma unroll
                for (int mt = 0; mt < 2; mt++) {
                    MMA_BF16(acc[mt][nt], afh[mt], bfh);
                    MMA_BF16(acc[mt][nt], afh[mt], bfl);
                    MMA_BF16(acc[mt][nt], afl[mt], bfh);
                }
            }
        }
        __syncthreads();
    }

    float* c1s = (float*)smem;     // alias stage region (GEMM done)
    #pragma unroll
    for (int mt = 0; mt < 2; mt++)
        #pragma unroll
        for (int nt = 0; nt < 4; nt++) {
            int col = wn*32 + nt*8 + 2*tig;
            if (col >= 96) continue;
            #pragma unroll
            for (int half = 0; half < 2; half++) {
                int row = bm + wm*32 + mt*16 + gid + half*8;
                float2 o;
                o.x = acc[mt][nt][half*2 + 0] + g_bh[col];
                o.y = acc[mt][nt][half*2 + 1] + g_bh[col + 1];
                if (col < 32) {
                    *(float2*)(recon + (size_t)row*32 + col) = o;
                } else {
                    int lrow = row - bm;
                    c1s[lrow*C1S + col - 32]     = fmaxf(o.x, 0.f);
                    c1s[lrow*C1S + col - 32 + 1] = fmaxf(o.y, 0.f);
                }
            }
        }
    __syncthreads();
    #pragma unroll
    for (int rr = 0; rr < 8; rr++) {
        int lrow = w*8 + rr;
        float s = c1s[lrow*C1S + lane]      * w2[lane]
                + c1s[lrow*C1S + 32 + lane] * w2[32 + lane];
        #pragma unroll
        for (int o = 16; o; o >>= 1) s += __shfl_xor_sync(0xffffffffu, s, o);
        if (lane == 0) clsOut[bm + lrow] = sigmoidf_(s + b2[0]);
    }
}

// ======================= fused GH GEMM + register GRU (t>=1) =================
// A tile = HS rows at time t-1 (packed hi/lo); writes HS at time t only.
#define GH_A64  (64*SRW2)              /* 2560 ushorts */
#define GH_B384 (384*SRW2)             /* 15360 ushorts */
#define GH_STG2 (2*GH_A64 + 2*GH_B384) /* 35840 ushorts */
#define GH_SMEM (2*GH_STG2*2)          /* 143360 B */

__global__ void __launch_bounds__(512, 1) ghgru_kernel(
    int t, const float* __restrict__ b_hh)
{
    extern __shared__ ushort_t smem[];
    uint32_t smem_b;
    asm("{ .reg .u64 t; cvta.to.shared.u64 t, %1; cvt.u32.u64 %0, t; }"
        : "=r"(smem_b) : "l"(smem));

    const int tid  = threadIdx.x;
    const int lane = tid & 31;
    const int w    = tid >> 5;
    const int gid  = lane >> 2;
    const int tig  = lane & 3;
    const int wm   = w >> 2;
    const int wn   = w & 3;
    const int bm   = blockIdx.x * 64;

    float acc[3][4][4];
    #pragma unroll
    for (int g = 0; g < 3; g++)
        #pragma unroll
        for (int j = 0; j < 4; j++)
            #pragma unroll
            for (int k = 0; k < 4; k++) acc[g][j][k] = 0.f;

    auto issue_copy = [&](int kc) {
        const uint32_t sb = smem_b + (uint32_t)((kc & 1) * GH_STG2) * 2u;
        // A: HS rows at t-1: 64 rows x 4 segs x 2 arrays = 512 -> 1/thread
        {
            int arr = tid >> 8;              // 0=hi 1=lo
            int i   = tid & 255;
            int row = i >> 2, seg = i & 3;
            uint32_t soff = (uint32_t)(arr * GH_A64 + row * SRW2 + seg * 8) * 2u;
            int grow = bm + row;
            const ushort_t* src = (arr ? g_HSlo : g_HShi)
                + ((size_t)min(grow, NNODES - 1) * 8 + (t - 1)) * 128 + kc * 32 + seg * 8;
            CP_ASYNC16(sb + soff, src, (grow < NNODES) ? 16 : 0);
        }
        // B: 384 rows x 4 segs x 2 arrays = 3072 -> 6/thread
        #pragma unroll
        for (int h = 0; h < 6; h++) {
            int i   = tid + h * 512;
            int arr = i >= 1536;
            int j   = arr ? i - 1536 : i;
            int row = j >> 2, seg = j & 3;
            uint32_t soff = (uint32_t)(2*GH_A64 + arr * GH_B384 + row * SRW2 + seg * 8) * 2u;
            const ushort_t* src = (arr ? g_Whhlo : g_Whhhi)
                                + (size_t)row * 128 + kc * 32 + seg * 8;
            CP_ASYNC16(sb + soff, src, 16);
        }
        CP_COMMIT();
    };

    issue_copy(0);
    for (int kc = 0; kc < 4; kc++) {
        if (kc + 1 < 4) { issue_copy(kc + 1); CP_WAIT1(); } else { CP_WAIT0(); }
        __syncthreads();
        const ushort_t* Ahi = smem + (kc & 1) * GH_STG2;
        const ushort_t* Alo = Ahi + GH_A64;
        const ushort_t* Bhi = Ahi + 2*GH_A64;
        const ushort_t* Blo = Bhi + GH_B384;
        #pragma unroll
        for (int ks = 0; ks < 2; ks++) {
            const int kk = ks*16 + tig*2;
            uint32_t afh[4], afl[4];
            LD_A4(afh, Ahi, SRW2, wm*16 + gid, kk);
            LD_A4(afl, Alo, SRW2, wm*16 + gid, kk);
            #pragma unroll
            for (int g = 0; g < 3; g++) {
                #pragma unroll
                for (int nt = 0; nt < 4; nt++) {
                    int cb = g*128 + wn*32 + nt*8 + gid;
                    uint32_t bfh[2], bfl[2];
                    LD_B2(bfh, Bhi, SRW2, cb, kk);
                    LD_B2(bfl, Blo, SRW2, cb, kk);
                    MMA_BF16(acc[g][nt], afh, bfh);
                    MMA_BF16(acc[g][nt], afh, bfl);
                    MMA_BF16(acc[g][nt], afl, bfh);
                }
            }
        }
        __syncthreads();
    }

    #pragma unroll
    for (int nt = 0; nt < 4; nt++) {
        int col = wn*32 + nt*8 + 2*tig;
        float2 bhr = *(const float2*)(b_hh + col);
        float2 bhz = *(const float2*)(b_hh + 128 + col);
        float2 bhn = *(const float2*)(b_hh + 256 + col);
        #pragma unroll
        for (int half = 0; half < 2; half++) {
            int node = bm + wm*16 + gid + half*8;
            if (node >= NNODES) continue;
            size_t m  = (size_t)node*8 + t;
            size_t mp = m - 1;                 // t-1 HS row
            float2 gxr = *(const float2*)(g_GX + m*384 + col);
            float2 gxz = *(const float2*)(g_GX + m*384 + 128 + col);
            float2 gxn = *(const float2*)(g_GX + m*384 + 256 + col);
            uint32_t phi = *(const uint32_t*)&g_HShi[mp*128 + col];
            uint32_t plo = *(const uint32_t*)&g_HSlo[mp*128 + col];
            float2 h = bjoin2(phi, plo);
            float ghr0 = acc[0][nt][half*2+0] + bhr.x, ghr1 = acc[0][nt][half*2+1] + bhr.y;
            float ghz0 = acc[1][nt][half*2+0] + bhz.x, ghz1 = acc[1][nt][half*2+1] + bhz.y;
            float ghn0 = acc[2][nt][half*2+0] + bhn.x, ghn1 = acc[2][nt][half*2+1] + bhn.y;
            float r0 = sigmoidf_(gxr.x + ghr0), r1 = sigmoidf_(gxr.y + ghr1);
            float z0 = sigmoidf_(gxz.x + ghz0), z1 = sigmoidf_(gxz.y + ghz1);
            float n0 = tanhf(gxn.x + r0*ghn0),  n1 = tanhf(gxn.y + r1*ghn1);
            float hn0 = (1.f - z0)*n0 + z0*h.x;
            float hn1 = (1.f - z1)*n1 + z1*h.y;
            uint32_t hi, lo;
            bsplit2(hn0, hn1, hi, lo);
            *(uint32_t*)&g_HShi[m*128 + col] = hi;
            *(uint32_t*)&g_HSlo[m*128 + col] = lo;
        }
    }
}

// ======================= launch ==============================================
extern "C" void kernel_launch(void* const* d_in, const int* in_sizes, int n_in,
                              void* d_out, int out_size)
{
    const float* x     = (const float*)d_in[0];
    const void*  ei    = d_in[1];
    const float* Wl    = (const float*)d_in[2];
    const float* bl    = (const float*)d_in[3];
    const float* Wr    = (const float*)d_in[4];
    const float* W_ih  = (const float*)d_in[5];
    const float* b_ih  = (const float*)d_in[6];
    const float* W_hh  = (const float*)d_in[7];
    const float* b_hh  = (const float*)d_in[8];
    const float* W_rec = (const float*)d_in[9];
    const float* b_rec = (const float*)d_in[10];
    const float* W_c1  = (const float*)d_in[11];
    const float* b_c1  = (const float*)d_in[12];
    const float* W_c2  = (const float*)d_in[13];
    const float* b_c2  = (const float*)d_in[14];

    float* out      = (float*)d_out;
    float* outRecon = out;
    float* outCls   = out + (size_t)MROWS * COUT;

    cudaFuncSetAttribute(spgx_kernel,  cudaFuncAttributeMaxDynamicSharedMemorySize, SPX_SMEM);
    cudaFuncSetAttribute(head_kernel,  cudaFuncAttributeMaxDynamicSharedMemorySize, HEAD_SMEM);
    cudaFuncSetAttribute(ghgru_kernel, cudaFuncAttributeMaxDynamicSharedMemorySize, GH_SMEM);

    // graph + weight prep
    detect_kernel<<<1, 1>>>(ei);
    zero_kernel<<<256, 256>>>();
    convcount_kernel<<<(EDGES + 255)/256, 256>>>(ei);
    wcat2_kernel<<<(128*64 + 255)/256, 256>>>(Wl, Wr);
    wih2_kernel<<<(384*128 + 255)/256, 256>>>(W_ih);
    whh2_kernel<<<(384*128 + 255)/256, 256>>>(W_hh);
    whd2_kernel<<<(96*128 + 255)/256, 256>>>(W_rec, b_rec, W_c1, b_c1);
    scan_kernel<<<1, 1024>>>();
    fill_kernel<<<(EDGES + 255)/256, 256>>>();
    gather_kernel<<<NNODES, 256>>>(x);

    // fused SP + GX + t=0 GRU
    spgx_kernel<<<MROWS/128, 512, SPX_SMEM>>>(bl, b_ih, b_hh);

    // recurrence t=1..7
    for (int t = 1; t < TT; t++)
        ghgru_kernel<<<(NNODES + 63)/64, 512, GH_SMEM>>>(t, b_hh);

    // heads
    head_kernel<<<MROWS/128, 512, HEAD_SMEM>>>(W_c2, b_c2, outRecon, outCls);
}

// round 17
// speedup vs baseline: 1.1319x; 1.0606x over previous
#include <cuda_runtime.h>
#include <cuda_bf16.h>
#include <math.h>
#include <stdint.h>

#define NNODES 50000
#define TT 8
#define HH 128
#define COUT 32
#define EDGES 800000
#define MROWS 400000

typedef unsigned short ushort_t;

// ======================= scratch (device globals) ============================
__device__ int   g_is64;
__device__ int   g_src[EDGES];
__device__ int   g_dst[EDGES];
__device__ int   g_cnt[NNODES];
__device__ int   g_off[NNODES];
__device__ int   g_cur[NNODES];
__device__ int   g_adj[EDGES];
__device__ float g_GX [(size_t)MROWS*3*HH];    // [m, 384] fp32 (t>=1 rows only)
__device__ float g_bh [96];
// packed-bf16 hi/lo operand arrays
__device__ ushort_t g_AXhi[(size_t)MROWS*64],   g_AXlo[(size_t)MROWS*64];
__device__ ushort_t g_Wcathi[128*64],           g_Wcatlo[128*64];
__device__ ushort_t g_Wihhi[384*128],           g_Wihlo[384*128];
__device__ ushort_t g_Whhhi[384*128],           g_Whhlo[384*128];
__device__ ushort_t g_Whdhi[96*128],            g_Whdlo[96*128];
__device__ ushort_t g_HShi[(size_t)MROWS*128],  g_HSlo[(size_t)MROWS*128];

// ======================= helpers =============================================
__device__ __forceinline__ void bsplit1(float v, ushort_t& h, ushort_t& l) {
    __nv_bfloat16 hb = __float2bfloat16_rn(v);
    __nv_bfloat16 lb = __float2bfloat16_rn(v - __bfloat162float(hb));
    h = __bfloat16_as_ushort(hb); l = __bfloat16_as_ushort(lb);
}
__device__ __forceinline__ void bsplit2(float v0, float v1, uint32_t& hi, uint32_t& lo) {
    ushort_t h0, l0, h1, l1;
    bsplit1(v0, h0, l0); bsplit1(v1, h1, l1);
    hi = ((uint32_t)h1 << 16) | h0;
    lo = ((uint32_t)l1 << 16) | l0;
}
__device__ __forceinline__ float2 bjoin2(uint32_t hi, uint32_t lo) {
    float2 r;
    r.x = __bfloat162float(__ushort_as_bfloat16((ushort_t)(hi & 0xffff)))
        + __bfloat162float(__ushort_as_bfloat16((ushort_t)(lo & 0xffff)));
    r.y = __bfloat162float(__ushort_as_bfloat16((ushort_t)(hi >> 16)))
        + __bfloat162float(__ushort_as_bfloat16((ushort_t)(lo >> 16)));
    return r;
}
#define MMA_BF16(C, Af, Bf) \
    asm volatile( \
        "mma.sync.aligned.m16n8k16.row.col.f32.bf16.bf16.f32 " \
        "{%0,%1,%2,%3}, {%4,%5,%6,%7}, {%8,%9}, {%0,%1,%2,%3};" \
        : "+f"((C)[0]), "+f"((C)[1]), "+f"((C)[2]), "+f"((C)[3]) \
        : "r"((Af)[0]), "r"((Af)[1]), "r"((Af)[2]), "r"((Af)[3]), \
          "r"((Bf)[0]), "r"((Bf)[1]))
#define CP_ASYNC16(dst, src, sz) \
    asm volatile("cp.async.ca.shared.global [%0], [%1], 16, %2;" \
                 :: "r"(dst), "l"(src), "r"(sz))
#define CP_COMMIT() asm volatile("cp.async.commit_group;" ::: "memory")
#define CP_WAIT1()  asm volatile("cp.async.wait_group 1;" ::: "memory")
#define CP_WAIT0()  asm volatile("cp.async.wait_group 0;" ::: "memory")
__device__ __forceinline__ float sigmoidf_(float v) { return 1.f / (1.f + expf(-v)); }

#define LD_A4(af, P, S2, r0, kk) do { \
    (af)[0] = *(const uint32_t*)&(P)[ (r0)    *(S2) + (kk)    ]; \
    (af)[1] = *(const uint32_t*)&(P)[((r0)+8) *(S2) + (kk)    ]; \
    (af)[2] = *(const uint32_t*)&(P)[ (r0)    *(S2) + (kk) + 8]; \
    (af)[3] = *(const uint32_t*)&(P)[((r0)+8) *(S2) + (kk) + 8]; \
} while (0)
#define LD_B2(bf, P, S2, cb, kk) do { \
    (bf)[0] = *(const uint32_t*)&(P)[(cb)*(S2) + (kk)    ]; \
    (bf)[1] = *(const uint32_t*)&(P)[(cb)*(S2) + (kk) + 8]; \
} while (0)

// ======================= edge prep ===========================================
__global__ void detect_kernel(const void* ei) {
    const unsigned long long* p = (const unsigned long long*)ei;
    int is64 = 1;
    for (int i = 0; i < 1024; i++)
        if ((p[i] >> 32) != 0ull) { is64 = 0; break; }
    g_is64 = is64;
}
__global__ void zero_kernel() {
    int idx = blockIdx.x * blockDim.x + threadIdx.x;
    int stride = gridDim.x * blockDim.x;
    for (int i = idx; i < NNODES; i += stride) g_cnt[i] = 0;
}
__global__ void convcount_kernel(const void* ei) {
    int e = blockIdx.x * blockDim.x + threadIdx.x;
    if (e >= EDGES) return;
    int s, d;
    if (g_is64) {
        const long long* p = (const long long*)ei;
        s = (int)p[e]; d = (int)p[EDGES + e];
    } else {
        const int* p = (const int*)ei;
        s = p[e]; d = p[EDGES + e];
    }
    s = min(max(s, 0), NNODES - 1);
    d = min(max(d, 0), NNODES - 1);
    g_src[e] = s;
    g_dst[e] = d;
    atomicAdd(&g_cnt[d], 1);
}
__global__ void scan_kernel() {
    __shared__ int partial[1024];
    const int CH = (NNODES + 1023) / 1024;
    int t = threadIdx.x;
    int begin = t * CH;
    int end   = min(begin + CH, NNODES);
    int s = 0;
    for (int i = begin; i < end; i++) s += g_cnt[i];
    partial[t] = s;
    __syncthreads();
    #pragma unroll
    for (int d = 1; d < 1024; d <<= 1) {
        int v = (t >= d) ? partial[t - d] : 0;
        __syncthreads();
        partial[t] += v;
        __syncthreads();
    }
    int off = partial[t] - s;
    for (int i = begin; i < end; i++) {
        g_off[i] = off;
        g_cur[i] = off;
        off += g_cnt[i];
    }
}
__global__ void fill_kernel() {
    int e = blockIdx.x * blockDim.x + threadIdx.x;
    if (e >= EDGES) return;
    int pos = atomicAdd(&g_cur[g_dst[e]], 1);
    g_adj[pos] = g_src[e];
}
__global__ void __launch_bounds__(256) gather_kernel(const float* __restrict__ x) {
    int n   = blockIdx.x;
    int idx = threadIdx.x;
    int beg = g_off[n];
    int cnt = g_cnt[n];
    float s = 0.f;
    for (int p = beg; p < beg + cnt; p++) {
        int src = g_adj[p];
        s += x[(size_t)src * 256 + idx];
    }
    float dg = fmaxf((float)cnt, 1.f);
    int t = idx >> 5, c = idx & 31;
    size_t m = (size_t)n * 8 + t;
    ushort_t h, l;
    bsplit1(s / dg, h, l);
    g_AXhi[m*64 + c] = h;      g_AXlo[m*64 + c] = l;
    bsplit1(x[(size_t)n * 256 + idx], h, l);
    g_AXhi[m*64 + 32 + c] = h; g_AXlo[m*64 + 32 + c] = l;
}
// weight conversions
__global__ void wcat2_kernel(const float* __restrict__ Wl, const float* __restrict__ Wr) {
    int idx = blockIdx.x * blockDim.x + threadIdx.x;
    if (idx >= 128*64) return;
    int j = idx >> 6, c = idx & 63;
    float v = (c < 32) ? Wl[j*32 + c] : Wr[j*32 + (c-32)];
    bsplit1(v, g_Wcathi[idx], g_Wcatlo[idx]);
}
__global__ void wih2_kernel(const float* __restrict__ W_ih) {
    int idx = blockIdx.x * blockDim.x + threadIdx.x;
    if (idx >= 384*128) return;
    bsplit1(W_ih[idx], g_Wihhi[idx], g_Wihlo[idx]);
}
__global__ void whh2_kernel(const float* __restrict__ W_hh) {
    int idx = blockIdx.x * blockDim.x + threadIdx.x;
    if (idx >= 384*128) return;
    bsplit1(W_hh[idx], g_Whhhi[idx], g_Whhlo[idx]);
}
__global__ void whd2_kernel(const float* __restrict__ W_rec, const float* __restrict__ b_rec,
                            const float* __restrict__ W_c1,  const float* __restrict__ b_c1) {
    int idx = blockIdx.x * blockDim.x + threadIdx.x;
    if (idx < 96*128) {
        int r = idx >> 7, k = idx & 127;
        float v = (r < 32) ? W_rec[r*128 + k] : W_c1[(r-32)*128 + k];
        bsplit1(v, g_Whdhi[idx], g_Whdlo[idx]);
    }
    if (idx < 96) g_bh[idx] = (idx < 32) ? b_rec[idx] : b_c1[idx - 32];
}

// ======================= tiling constants ====================================
#define SRW2 40                       /* ushort stride for 32-k chunk rows */
#define A128 (128*SRW2)               /* 5120 ushorts */
#define STG2 (4*A128)                 /* Ahi,Alo,Bhi,Blo = 20480 ushorts */
#define C1S  72

// ======================= fused SP+GX(+t0 GRU) kernel =========================
#define SPX_ST2  136
#define SPHI_OFF (2*STG2)                       /* 40960 ushorts */
#define SPLO_OFF (SPHI_OFF + 128*SPX_ST2)       /* 58368 */
#define GX0_OFF  (SPLO_OFF + 128*SPX_ST2)       /* 75776 ushorts -> float buf  */
#define SPX_SMEM (GX0_OFF*2 + 16*392*4)         /* 151552 + 25088 = 176640 B */

__global__ void __launch_bounds__(512, 1) spgx_kernel(
    const float* __restrict__ bl, const float* __restrict__ b_ih,
    const float* __restrict__ b_hh)
{
    extern __shared__ ushort_t smem[];
    uint32_t smem_b;
    asm("{ .reg .u64 t; cvta.to.shared.u64 t, %1; cvt.u32.u64 %0, t; }"
        : "=r"(smem_b) : "l"(smem));

    const int tid  = threadIdx.x;
    const int lane = tid & 31;
    const int w    = tid >> 5;
    const int gid  = lane >> 2;
    const int tig  = lane & 3;
    const int wm   = w >> 2;
    const int wn   = w & 3;
    const int bm   = blockIdx.x * 128;
    ushort_t* SPhi = smem + SPHI_OFF;
    ushort_t* SPlo = smem + SPLO_OFF;
    float*    gx0  = (float*)(smem + GX0_OFF);   // [16][392] t=0 gate stash

    float acc[2][4][4];
    #pragma unroll
    for (int i = 0; i < 2; i++)
        #pragma unroll
        for (int j = 0; j < 4; j++)
            #pragma unroll
            for (int k = 0; k < 4; k++) acc[i][j][k] = 0.f;

    // ---------------- phase 1: SP = relu(AX @ Wcat^T + bl) ----------------
    auto issue_copy1 = [&](int kc) {
        const uint32_t sb = smem_b + (uint32_t)((kc & 1) * STG2) * 2u;
        int row = tid >> 2, seg = tid & 3;
        uint32_t soff = (uint32_t)(row * SRW2 + seg * 8) * 2u;
        size_t goff = (size_t)(bm + row) * 64 + kc * 32 + seg * 8;
        size_t woff = (size_t)row * 64 + kc * 32 + seg * 8;
        CP_ASYNC16(sb + soff,                    g_AXhi  + goff, 16);
        CP_ASYNC16(sb + (uint32_t)A128*2 + soff, g_AXlo  + goff, 16);
        CP_ASYNC16(sb + (uint32_t)(2*A128)*2 + soff, g_Wcathi + woff, 16);
        CP_ASYNC16(sb + (uint32_t)(3*A128)*2 + soff, g_Wcatlo + woff, 16);
        CP_COMMIT();
    };

    issue_copy1(0);
    for (int kc = 0; kc < 2; kc++) {
        if (kc == 0) { issue_copy1(1); CP_WAIT1(); } else { CP_WAIT0(); }
        __syncthreads();
        const ushort_t* Ahi = smem + (kc & 1) * STG2;
        const ushort_t* Alo = Ahi + A128;
        const ushort_t* Bhi = Ahi + 2*A128;
        const ushort_t* Blo = Ahi + 3*A128;
        #pragma unroll
        for (int ks = 0; ks < 2; ks++) {
            const int kk = ks*16 + tig*2;
            uint32_t afh[2][4], afl[2][4];
            #pragma unroll
            for (int mt = 0; mt < 2; mt++) {
                LD_A4(afh[mt], Ahi, SRW2, wm*32 + mt*16 + gid, kk);
                LD_A4(afl[mt], Alo, SRW2, wm*32 + mt*16 + gid, kk);
            }
            #pragma unroll
            for (int nt = 0; nt < 4; nt++) {
                int cb = wn*32 + nt*8 + gid;
                uint32_t bfh[2], bfl[2];
                LD_B2(bfh, Bhi, SRW2, cb, kk);
                LD_B2(bfl, Blo, SRW2, cb, kk);
                #pragma unroll
                for (int mt = 0; mt < 2; mt++) {
                    MMA_BF16(acc[mt][nt], afh[mt], bfh);
                    MMA_BF16(acc[mt][nt], afh[mt], bfl);
                    MMA_BF16(acc[mt][nt], afl[mt], bfh);
                }
            }
        }
        __syncthreads();
    }
    #pragma unroll
    for (int mt = 0; mt < 2; mt++)
        #pragma unroll
        for (int nt = 0; nt < 4; nt++) {
            int col = wn*32 + nt*8 + 2*tig;
            #pragma unroll
            for (int half = 0; half < 2; half++) {
                int lrow = wm*32 + mt*16 + gid + half*8;
                float vx = fmaxf(acc[mt][nt][half*2 + 0] + bl[col],     0.f);
                float vy = fmaxf(acc[mt][nt][half*2 + 1] + bl[col + 1], 0.f);
                uint32_t hi, lo;
                bsplit2(vx, vy, hi, lo);
                *(uint32_t*)&SPhi[lrow*SPX_ST2 + col] = hi;
                *(uint32_t*)&SPlo[lrow*SPX_ST2 + col] = lo;
            }
        }
    __syncthreads();

    // ---------------- phase 2: GX = SP @ W_ih^T + b_ih (3 N-subtiles) -------
    auto issue_copyB = [&](int idx) {   // idx = nt*4 + kc
        int nt = idx >> 2, kc = idx & 3;
        const uint32_t sb = smem_b + (uint32_t)((idx & 1) * STG2) * 2u;
        int row = tid >> 2, seg = tid & 3;
        uint32_t soff = (uint32_t)(row * SRW2 + seg * 8) * 2u;
        size_t goff = (size_t)(nt*128 + row) * 128 + kc * 32 + seg * 8;
        CP_ASYNC16(sb + (uint32_t)(2*A128)*2 + soff, g_Wihhi + goff, 16);
        CP_ASYNC16(sb + (uint32_t)(3*A128)*2 + soff, g_Wihlo + goff, 16);
        CP_COMMIT();
    };

    issue_copyB(0);
    for (int nt3 = 0; nt3 < 3; nt3++) {
        #pragma unroll
        for (int i = 0; i < 2; i++)
            #pragma unroll
            for (int j = 0; j < 4; j++)
                #pragma unroll
                for (int k = 0; k < 4; k++) acc[i][j][k] = 0.f;

        for (int kc = 0; kc < 4; kc++) {
            int idx = nt3*4 + kc;
            if (idx + 1 < 12) { issue_copyB(idx + 1); CP_WAIT1(); } else { CP_WAIT0(); }
            __syncthreads();
            const ushort_t* Bhi = smem + (idx & 1) * STG2 + 2*A128;
            const ushort_t* Blo = Bhi + A128;

            #pragma unroll
            for (int ks = 0; ks < 2; ks++) {
                const int ka = kc*32 + ks*16 + tig*2;
                const int kb = ks*16 + tig*2;
                uint32_t afh[2][4], afl[2][4];
                #pragma unroll
                for (int mt = 0; mt < 2; mt++) {
                    LD_A4(afh[mt], SPhi, SPX_ST2, wm*32 + mt*16 + gid, ka);
                    LD_A4(afl[mt], SPlo, SPX_ST2, wm*32 + mt*16 + gid, ka);
                }
                #pragma unroll
                for (int nt = 0; nt < 4; nt++) {
                    int cb = wn*32 + nt*8 + gid;
                    uint32_t bfh[2], bfl[2];
                    LD_B2(bfh, Bhi, SRW2, cb, kb);
                    LD_B2(bfl, Blo, SRW2, cb, kb);
                    #pragma unroll
                    for (int mt = 0; mt < 2; mt++) {
                        MMA_BF16(acc[mt][nt], afh[mt], bfh);
                        MMA_BF16(acc[mt][nt], afh[mt], bfl);
                        MMA_BF16(acc[mt][nt], afl[mt], bfh);
                    }
                }
            }
            __syncthreads();
        }

        // write GX subtile (t>=1 rows); stash t=0 rows' gates in smem
        #pragma unroll
        for (int mt = 0; mt < 2; mt++)
            #pragma unroll
            for (int nt = 0; nt < 4; nt++) {
                int col = nt3*128 + wn*32 + nt*8 + 2*tig;
                #pragma unroll
                for (int half = 0; half < 2; half++) {
                    int lrow = wm*32 + mt*16 + gid + half*8;
                    int row  = bm + lrow;
                    float ox = acc[mt][nt][half*2 + 0] + b_ih[col];
                    float oy = acc[mt][nt][half*2 + 1] + b_ih[col + 1];
                    if ((lrow & 7) == 0) {
                        int rr = lrow >> 3;
                        gx0[rr*392 + col]     = ox;
                        gx0[rr*392 + col + 1] = oy;
                    } else {
                        float2 o = make_float2(ox, oy);
                        *(float2*)(g_GX + (size_t)row*384 + col) = o;
                    }
                }
            }
    }
    __syncthreads();

    // ---------------- t=0 GRU (gh = b_hh), write HS ----------------
    for (int e = tid; e < 16*64; e += 512) {
        int rr = e >> 6;
        int j  = (e & 63) * 2;
        size_t m = (size_t)(bm + rr*8);
        float r0 = sigmoidf_(gx0[rr*392 + j]       + b_hh[j]);
        float r1 = sigmoidf_(gx0[rr*392 + j + 1]   + b_hh[j + 1]);
        float z0 = sigmoidf_(gx0[rr*392 + 128 + j]     + b_hh[128 + j]);
        float z1 = sigmoidf_(gx0[rr*392 + 128 + j + 1] + b_hh[128 + j + 1]);
        float n0 = tanhf(gx0[rr*392 + 256 + j]     + r0 * b_hh[256 + j]);
        float n1 = tanhf(gx0[rr*392 + 256 + j + 1] + r1 * b_hh[256 + j + 1]);
        float h0 = (1.f - z0)*n0;
        float h1 = (1.f - z1)*n1;
        uint32_t hi, lo;
        bsplit2(h0, h1, hi, lo);
        *(uint32_t*)&g_HShi[m*128 + j] = hi;
        *(uint32_t*)&g_HSlo[m*128 + j] = lo;
    }
}

// ======================= head GEMM + fused cls ===============================
#define HEAD_SMEM (2*STG2*2)          /* 81920 B */
__global__ void __launch_bounds__(512, 1) head_kernel(
    const float* __restrict__ w2, const float* __restrict__ b2,
    float* __restrict__ recon, float* __restrict__ clsOut)
{
    extern __shared__ ushort_t smem[];
    uint32_t smem_b;
    asm("{ .reg .u64 t; cvta.to.shared.u64 t, %1; cvt.u32.u64 %0, t; }"
        : "=r"(smem_b) : "l"(smem));

    const int tid  = threadIdx.x;
    const int lane = tid & 31;
    const int w    = tid >> 5;
    const int gid  = lane >> 2;
    const int tig  = lane & 3;
    const int wm   = w >> 2;
    const int wn   = w & 3;
    const int bm   = blockIdx.x * 128;

    float acc[2][4][4];
    #pragma unroll
    for (int i = 0; i < 2; i++)
        #pragma unroll
        for (int j = 0; j < 4; j++)
            #pragma unroll
            for (int k = 0; k < 4; k++) acc[i][j][k] = 0.f;

    auto issue_copy = [&](int kc) {
        const uint32_t sb = smem_b + (uint32_t)((kc & 1) * STG2) * 2u;
        int row = tid >> 2, seg = tid & 3;
        uint32_t soff = (uint32_t)(row * SRW2 + seg * 8) * 2u;
        size_t aoff = (size_t)(bm + row) * 128 + kc * 32 + seg * 8;
        size_t woff = (size_t)min(row, 95) * 128 + kc * 32 + seg * 8;
        int wsz = (row < 96) ? 16 : 0;
        CP_ASYNC16(sb + soff,                        g_HShi + aoff, 16);
        CP_ASYNC16(sb + (uint32_t)A128*2 + soff,     g_HSlo + aoff, 16);
        CP_ASYNC16(sb + (uint32_t)(2*A128)*2 + soff, g_Whdhi + woff, wsz);
        CP_ASYNC16(sb + (uint32_t)(3*A128)*2 + soff, g_Whdlo + woff, wsz);
        CP_COMMIT();
    };

    issue_copy(0);
    for (int kc = 0; kc < 4; kc++) {
        if (kc + 1 < 4) { issue_copy(kc + 1); CP_WAIT1(); } else { CP_WAIT0(); }
        __syncthreads();
        const ushort_t* Ahi = smem + (kc & 1) * STG2;
        const ushort_t* Alo = Ahi + A128;
        const ushort_t* Bhi = Ahi + 2*A128;
        const ushort_t* Blo = Ahi + 3*A128;
        #pragma unroll
        for (int ks = 0; ks < 2; ks++) {
            const int kk = ks*16 + tig*2;
            uint32_t afh[2][4], afl[2][4];
            #pragma unroll
            for (int mt = 0; mt < 2; mt++) {
                LD_A4(afh[mt], Ahi, SRW2, wm*32 + mt*16 + gid, kk);
                LD_A4(afl[mt], Alo, SRW2, wm*32 + mt*16 + gid, kk);
            }
            #pragma unroll
            for (int nt = 0; nt < 4; nt++) {
                int cb = wn*32 + nt*8 + gid;
                uint32_t bfh[2], bfl[2];
                LD_B2(bfh, Bhi, SRW2, cb, kk);
                LD_B2(bfl, Blo, SRW2, cb, kk);
                #pragma unroll
                for (int mt = 0; mt < 2; mt++) {
                    MMA_BF16(acc[mt][nt], afh[mt], bfh);
                    MMA_BF16(acc[mt][nt], afh[mt], bfl);
                    MMA_BF16(acc[mt][nt], afl[mt], bfh);
                }
            }
        }
        __syncthreads();
    }

    float* c1s = (float*)smem;
    #pragma unroll
    for (int mt = 0; mt < 2; mt++)
        #pragma unroll
        for (int nt = 0; nt < 4; nt++) {
            int col = wn*32 + nt*8 + 2*tig;
            if (col >= 96) continue;
            #pragma unroll
            for (int half = 0; half < 2; half++) {
                int row = bm + wm*32 + mt*16 + gid + half*8;
                float2 o;
                o.x = acc[mt][nt][half*2 + 0] + g_bh[col];
                o.y = acc[mt][nt][half*2 + 1] + g_bh[col + 1];
                if (col < 32) {
                    *(float2*)(recon + (size_t)row*32 + col) = o;
                } else {
                    int lrow = row - bm;
                    c1s[lrow*C1S + col - 32]     = fmaxf(o.x, 0.f);
                    c1s[lrow*C1S + col - 32 + 1] = fmaxf(o.y, 0.f);
                }
            }
        }
    __syncthreads();
    #pragma unroll
    for (int rr = 0; rr < 8; rr++) {
        int lrow = w*8 + rr;
        float s = c1s[lrow*C1S + lane]      * w2[lane]
                + c1s[lrow*C1S + 32 + lane] * w2[32 + lane];
        #pragma unroll
        for (int o = 16; o; o >>= 1) s += __shfl_xor_sync(0xffffffffu, s, o);
        if (lane == 0) clsOut[bm + lrow] = sigmoidf_(s + b2[0]);
    }
}

// ======================= persistent GH GEMM + GRU (t = 1..7, ONE launch) =====
// CTA owns 64 nodes' timeline; h carried in persistent smem A-tile. Standard
// 2-buffer, 1-ahead cp.async pipeline (issue c+1 into opposite buffer only).
#define GH_B384 (384*SRW2)              /* 15360 ushorts (one array) */
#define PH_BSTG (2*GH_B384)             /* hi+lo per stage = 30720 ushorts */
#define PH_AOFF (2*PH_BSTG)             /* 61440 ushorts */
#define PH_AST  136
#define PH_ALO  (PH_AOFF + 64*PH_AST)   /* 70144 */
#define PH_SMEM ((PH_ALO + 64*PH_AST)*2) /* 157696 B */

__global__ void __launch_bounds__(512, 1) ghgru_kernel(const float* __restrict__ b_hh)
{
    extern __shared__ ushort_t smem[];
    uint32_t smem_b;
    asm("{ .reg .u64 t; cvta.to.shared.u64 t, %1; cvt.u32.u64 %0, t; }"
        : "=r"(smem_b) : "l"(smem));

    const int tid  = threadIdx.x;
    const int lane = tid & 31;
    const int w    = tid >> 5;
    const int gid  = lane >> 2;
    const int tig  = lane & 3;
    const int wm   = w >> 2;
    const int wn   = w & 3;
    const int bm   = blockIdx.x * 64;
    ushort_t* Ahi = smem + PH_AOFF;
    ushort_t* Alo = smem + PH_ALO;

    auto issueB = [&](int c) {
        const uint32_t sb = smem_b + (uint32_t)((c & 1) * PH_BSTG) * 2u;
        const int kc = c & 3;
        #pragma unroll
        for (int h = 0; h < 6; h++) {
            int i   = tid + h * 512;
            int arr = i >= 1536;
            int j   = arr ? i - 1536 : i;
            int row = j >> 2, seg = j & 3;
            uint32_t soff = (uint32_t)(arr * GH_B384 + row * SRW2 + seg * 8) * 2u;
            const ushort_t* src = (arr ? g_Whhlo : g_Whhhi)
                                + (size_t)row * 128 + kc * 32 + seg * 8;
            CP_ASYNC16(sb + soff, src, 16);
        }
        CP_COMMIT();
    };

    // initial A load: HS at t=0 -> persistent A tile; grouped with B chunk 0
    {
        #pragma unroll
        for (int h = 0; h < 4; h++) {
            int i   = tid + h * 512;          // 0..2047
            int arr = i >= 1024;
            int j   = arr ? i - 1024 : i;
            int row = j >> 4, seg = j & 15;   // 64 rows x 16 segs
            uint32_t soff = (uint32_t)((arr ? PH_ALO : PH_AOFF) + row * PH_AST + seg * 8) * 2u;
            int grow = bm + row;
            const ushort_t* src = (arr ? g_HSlo : g_HShi)
                                + (size_t)min(grow, NNODES - 1) * 8 * 128 + seg * 8;
            CP_ASYNC16(smem_b + soff, src, (grow < NNODES) ? 16 : 0);
        }
        issueB(0);
    }

    float acc[3][4][4];
    #pragma unroll
    for (int g = 0; g < 3; g++)
        #pragma unroll
        for (int j = 0; j < 4; j++)
            #pragma unroll
            for (int k = 0; k < 4; k++) acc[g][j][k] = 0.f;

    for (int c = 0; c < 28; c++) {
        if (c + 1 < 28) { issueB(c + 1); CP_WAIT1(); } else { CP_WAIT0(); }
        __syncthreads();
        const ushort_t* Bhi = smem + (c & 1) * PH_BSTG;
        const ushort_t* Blo = Bhi + GH_B384;
        const int kc = c & 3;

        #pragma unroll
        for (int ks = 0; ks < 2; ks++) {
            const int ka = kc*32 + ks*16 + tig*2;   // persistent A: full-K index
            const int kb = ks*16 + tig*2;
            uint32_t afh[4], afl[4];
            LD_A4(afh, Ahi, PH_AST, wm*16 + gid, ka);
            LD_A4(afl, Alo, PH_AST, wm*16 + gid, ka);
            #pragma unroll
            for (int g = 0; g < 3; g++) {
                #pragma unroll
                for (int nt = 0; nt < 4; nt++) {
                    int cb = g*128 + wn*32 + nt*8 + gid;
                    uint32_t bfh[2], bfl[2];
                    LD_B2(bfh, Bhi, SRW2, cb, kb);
                    LD_B2(bfl, Blo, SRW2, cb, kb);
                    MMA_BF16(acc[g][nt], afh, bfh);
                    MMA_BF16(acc[g][nt], afh, bfl);
                    MMA_BF16(acc[g][nt], afl, bfh);
                }
            }
        }
        __syncthreads();

        if ((c & 3) == 3) {
            const int t = (c >> 2) + 1;
            #pragma unroll
            for (int nt = 0; nt < 4; nt++) {
                int col = wn*32 + nt*8 + 2*tig;
                float2 bhr = *(const float2*)(b_hh + col);
                float2 bhz = *(const float2*)(b_hh + 128 + col);
                float2 bhn = *(const float2*)(b_hh + 256 + col);
                #pragma unroll
                for (int half = 0; half < 2; half++) {
                    int lrow = wm*16 + gid + half*8;
                    int node = bm + lrow;
                    if (node >= NNODES) continue;
                    size_t m = (size_t)node*8 + t;
                    float2 gxr = *(const float2*)(g_GX + m*384 + col);
                    float2 gxz = *(const float2*)(g_GX + m*384 + 128 + col);
                    float2 gxn = *(const float2*)(g_GX + m*384 + 256 + col);
                    uint32_t phi = *(const uint32_t*)&Ahi[lrow*PH_AST + col];
                    uint32_t plo = *(const uint32_t*)&Alo[lrow*PH_AST + col];
                    float2 h = bjoin2(phi, plo);
                    float ghr0 = acc[0][nt][half*2+0] + bhr.x, ghr1 = acc[0][nt][half*2+1] + bhr.y;
                    float ghz0 = acc[1][nt][half*2+0] + bhz.x, ghz1 = acc[1][nt][half*2+1] + bhz.y;
                    float ghn0 = acc[2][nt][half*2+0] + bhn.x, ghn1 = acc[2][nt][half*2+1] + bhn.y;
                    float r0 = sigmoidf_(gxr.x + ghr0), r1 = sigmoidf_(gxr.y + ghr1);
                    float z0 = sigmoidf_(gxz.x + ghz0), z1 = sigmoidf_(gxz.y + ghz1);
                    float n0 = tanhf(gxn.x + r0*ghn0),  n1 = tanhf(gxn.y + r1*ghn1);
                    float hn0 = (1.f - z0)*n0 + z0*h.x;
                    float hn1 = (1.f - z1)*n1 + z1*h.y;
                    uint32_t hi, lo;
                    bsplit2(hn0, hn1, hi, lo);
                    *(uint32_t*)&Ahi[lrow*PH_AST + col] = hi;
                    *(uint32_t*)&Alo[lrow*PH_AST + col] = lo;
                    *(uint32_t*)&g_HShi[m*128 + col] = hi;
                    *(uint32_t*)&g_HSlo[m*128 + col] = lo;
                }
            }
            #pragma unroll
            for (int g = 0; g < 3; g++)
                #pragma unroll
                for (int j = 0; j < 4; j++)
                    #pragma unroll
                    for (int k = 0; k < 4; k++) acc[g][j][k] = 0.f;
            __syncthreads();    // hn visible before next step's frag loads
        }
    }
}

// ======================= launch ==============================================
extern "C" void kernel_launch(void* const* d_in, const int* in_sizes, int n_in,
                              void* d_out, int out_size)
{
    const float* x     = (const float*)d_in[0];
    const void*  ei    = d_in[1];
    const float* Wl    = (const float*)d_in[2];
    const float* bl    = (const float*)d_in[3];
    const float* Wr    = (const float*)d_in[4];
    const float* W_ih  = (const float*)d_in[5];
    const float* b_ih  = (const float*)d_in[6];
    const float* W_hh  = (const float*)d_in[7];
    const float* b_hh  = (const float*)d_in[8];
    const float* W_rec = (const float*)d_in[9];
    const float* b_rec = (const float*)d_in[10];
    const float* W_c1  = (const float*)d_in[11];
    const float* b_c1  = (const float*)d_in[12];
    const float* W_c2  = (const float*)d_in[13];
    const float* b_c2  = (const float*)d_in[14];

    float* out      = (float*)d_out;
    float* outRecon = out;
    float* outCls   = out + (size_t)MROWS * COUT;

    cudaFuncSetAttribute(spgx_kernel,  cudaFuncAttributeMaxDynamicSharedMemorySize, SPX_SMEM);
    cudaFuncSetAttribute(head_kernel,  cudaFuncAttributeMaxDynamicSharedMemorySize, HEAD_SMEM);
    cudaFuncSetAttribute(ghgru_kernel, cudaFuncAttributeMaxDynamicSharedMemorySize, PH_SMEM);

    // graph + weight prep
    detect_kernel<<<1, 1>>>(ei);
    zero_kernel<<<256, 256>>>();
    convcount_kernel<<<(EDGES + 255)/256, 256>>>(ei);
    wcat2_kernel<<<(128*64 + 255)/256, 256>>>(Wl, Wr);
    wih2_kernel<<<(384*128 + 255)/256, 256>>>(W_ih);
    whh2_kernel<<<(384*128 + 255)/256, 256>>>(W_hh);
    whd2_kernel<<<(96*128 + 255)/256, 256>>>(W_rec, b_rec, W_c1, b_c1);
    scan_kernel<<<1, 1024>>>();
    fill_kernel<<<(EDGES + 255)/256, 256>>>();
    gather_kernel<<<NNODES, 256>>>(x);

    // fused SP + GX + t=0 GRU
    spgx_kernel<<<MROWS/128, 512, SPX_SMEM>>>(bl, b_ih, b_hh);

    // persistent recurrence t=1..7 in ONE launch
    ghgru_kernel<<<(NNODES + 63)/64, 512, PH_SMEM>>>(b_hh);

    // heads
    head_kernel<<<MROWS/128, 512, HEAD_SMEM>>>(W_c2, b_c2, outRecon, outCls);
}